// round 14
// baseline (speedup 1.0000x reference)
#include <cuda_runtime.h>

#define BB 16
#define GG 50
#define AA 81920
#define TT 128
#define PP 64
#define NNEGK 64
#define POSCAP 65536
#define HICAP 4096
#define HITHRESH 0.998f
#define NBK 512
#define MCAP 1024
#define DIRECT 256
#define APB 4096           // anchors per kA block
#define RPT (APB / 256)    // rounds per thread (16)
#define NCELL 1024         // 10-bit Morton cells (32x32)

// ---------------- device scratch (static, zero-init at load; kC resets) ----
static __device__ float              g_colmax[BB][AA];
static __device__ int                g_argg[BB][AA];      // valid only when cm>=0.7
static __device__ unsigned long long g_rowvk[BB][GG];     // (v_bits<<32)|(~a)      max
static __device__ unsigned long long g_lx[BB][GG];        // (~x1_bits<<32)|(~a)    max (== min x1, min a)
static __device__ unsigned long long g_rx[BB][GG];        // (x1_bits<<32)|(~a)     max
static __device__ int                g_poscnt[BB];
static __device__ int                g_posj[BB][POSCAP];
static __device__ float              g_posu[BB][POSCAP];
static __device__ int                g_hicnt[BB];
static __device__ float              g_hiv[BB][HICAP];
static __device__ int                g_hii[BB][HICAP];
static __device__ int                g_negavail[BB];
static __device__ float              g_fbu[BB][AA];       // fallback-only scratch

// ---------------- threefry2x32 (JAX partitionable) ----------------
__device__ __forceinline__ void threefry2x32(unsigned int k0, unsigned int k1,
                                             unsigned int x0, unsigned int x1,
                                             unsigned int &o0, unsigned int &o1) {
  const unsigned int ks0 = k0, ks1 = k1, ks2 = k0 ^ k1 ^ 0x1BD11BDAu;
  unsigned int v0 = x0 + ks0, v1 = x1 + ks1;
#define TFR(r) { v0 += v1; v1 = (v1 << (r)) | (v1 >> (32 - (r))); v1 ^= v0; }
  TFR(13) TFR(15) TFR(26) TFR(6)   v0 += ks1; v1 += ks2 + 1u;
  TFR(17) TFR(29) TFR(16) TFR(24)  v0 += ks2; v1 += ks0 + 2u;
  TFR(13) TFR(15) TFR(26) TFR(6)   v0 += ks0; v1 += ks1 + 3u;
  TFR(17) TFR(29) TFR(16) TFR(24)  v0 += ks1; v1 += ks2 + 4u;
  TFR(13) TFR(15) TFR(26) TFR(6)   v0 += ks2; v1 += ks0 + 5u;
#undef TFR
  o0 = v0; o1 = v1;
}

__device__ __forceinline__ float jax_uniform(uint2 key, unsigned int idx) {
  unsigned int o0, o1;
  threefry2x32(key.x, key.y, 0u, idx, o0, o1);
  unsigned int bits = o0 ^ o1;
  return __uint_as_float((bits >> 9) | 0x3F800000u) - 1.0f;
}

// keys = split(key(42), B); k1,k2 = split(keys[b])
__device__ __forceinline__ void derive_keys(int b, uint2 &k1, uint2 &k2) {
  unsigned int kb0, kb1, a0, a1, c0, c1;
  threefry2x32(0u, 42u, 0u, (unsigned int)b, kb0, kb1);
  threefry2x32(kb0, kb1, 0u, 0u, a0, a1);
  threefry2x32(kb0, kb1, 0u, 1u, c0, c1);
  k1 = make_uint2(a0, a1);
  k2 = make_uint2(c0, c1);
}

// ---------------- 10-bit Morton cell of (y1, x1): 32x32 grid ----------------
__device__ __forceinline__ int cell10(float y1, float x1) {
  int by = (int)(y1 * (32.0f / 961.0f));
  int bx = (int)(x1 * (32.0f / 1001.0f));
  by = by < 0 ? 0 : (by > 31 ? 31 : by);
  bx = bx < 0 ? 0 : (bx > 31 ? 31 : bx);
  int m = 0;
  #pragma unroll
  for (int i = 0; i < 5; i++)
    m |= (((by >> i) & 1) << (2 * i + 1)) | (((bx >> i) & 1) << (2 * i));
  return m;
}

// ---- pass A: in-block Morton sort (4096 anchors) + warp-coherent IoU ------
__global__ void kA(const float* __restrict__ gt_boxes, const float* __restrict__ anchors) {
  const int b = blockIdx.y;
  const int t = threadIdx.x;
  const int abase = blockIdx.x * APB;
  __shared__ float4 sq4[GG];     // (y1, x1, y2, x2)
  __shared__ float  sarea[GG];
  __shared__ int    s_tg[GG];
  __shared__ int    s_nt;
  __shared__ int    s_negc;
  __shared__ unsigned long long s_rk[GG];
  __shared__ unsigned long long s_lk[GG];   // complemented encoding, max
  __shared__ unsigned long long s_rr[GG];
  __shared__ uint2  s_k1, s_k2;
  __shared__ unsigned short scell[APB];
  __shared__ unsigned short sperm[APB];
  __shared__ int    shist[NCELL];
  __shared__ int    saux[256];

  if (t == 0) { s_nt = 0; s_negc = 0; derive_keys(b, s_k1, s_k2); }
  #pragma unroll
  for (int i = 0; i < NCELL / 256; i++) shist[i * 256 + t] = 0;
  __syncthreads();
  for (int g = t; g < GG; g += 256) {
    const float* gp = gt_boxes + ((long)b * GG + g) * 5;
    float q0 = gp[0], q1 = gp[1], q2 = gp[2], q3 = gp[3], tg = gp[4];
    sq4[g] = make_float4(q0, q1, q2, q3);
    sarea[g] = __fmul_rn(__fsub_rn(q3, q1), __fsub_rn(q2, q0));
    s_rk[g] = 0ull; s_lk[g] = 0ull; s_rr[g] = 0ull;
    if (tg > 0.0f) { int k = atomicAdd(&s_nt, 1); s_tg[k] = g; }
  }
  __syncthreads();

  const float4* ap = reinterpret_cast<const float4*>(anchors) + (long)b * AA;

  // ---- pass 1: local histogram (coalesced anchor loads) ----
  #pragma unroll 4
  for (int r = 0; r < RPT; r++) {
    const int i = r * 256 + t;
    const float4 an = ap[abase + i];
    const int c = cell10(an.x, an.y);
    scell[i] = (unsigned short)c;
    atomicAdd(&shist[c], 1);
  }
  __syncthreads();

  // ---- exclusive scan over 1024 bins (4 bins/thread + 256-wide HS scan) ----
  {
    int c0 = shist[4 * t], c1 = shist[4 * t + 1], c2 = shist[4 * t + 2], c3 = shist[4 * t + 3];
    int tot = c0 + c1 + c2 + c3;
    saux[t] = tot;
    __syncthreads();
    int val = tot;
    for (int off = 1; off < 256; off <<= 1) {
      int y = (t >= off) ? saux[t - off] : 0;
      __syncthreads();
      val += y;
      saux[t] = val;
      __syncthreads();
    }
    int base = val - tot;     // exclusive across thread groups
    shist[4 * t]     = base;
    shist[4 * t + 1] = base + c0;
    shist[4 * t + 2] = base + c0 + c1;
    shist[4 * t + 3] = base + c0 + c1 + c2;
  }
  __syncthreads();

  // ---- pass 2: scatter local permutation ----
  #pragma unroll 4
  for (int r = 0; r < RPT; r++) {
    const int i = r * 256 + t;
    const int slot = atomicAdd(&shist[scell[i]], 1);
    sperm[slot] = (unsigned short)i;
  }
  __syncthreads();

  // ---- main: RPT rounds of warp-coherent processing ----
  const int nt = s_nt;
  const int lane = t & 31;
  int negc = 0;
  #pragma unroll 1
  for (int r = 0; r < RPT; r++) {
    const int a = abase + (int)sperm[r * 256 + t];
    const float4 an = ap[a];                 // gather; L1-resident
    const float areaa = __fmul_rn(__fsub_rn(an.w, an.y), __fsub_rn(an.z, an.x));

    // warp bounding box (coords >= 0: float bits order-preserving)
    const float wy1min = __uint_as_float(__reduce_min_sync(0xFFFFFFFFu, __float_as_uint(an.x)));
    const float wy2max = __uint_as_float(__reduce_max_sync(0xFFFFFFFFu, __float_as_uint(an.z)));
    const float wx1min = __uint_as_float(__reduce_min_sync(0xFFFFFFFFu, __float_as_uint(an.y)));
    const float wx2max = __uint_as_float(__reduce_max_sync(0xFFFFFFFFu, __float_as_uint(an.w)));

    // per-warp GT survival mask via ballots
    unsigned long long wmask = 0ull;
    for (int base = 0; base < nt; base += 32) {
      int k = base + lane;
      bool pass = false;
      if (k < nt) {
        const float4 q = sq4[s_tg[k]];
        pass = (q.w > wx1min) && (wx2max > q.y) && (q.z > wy1min) && (wy2max > q.x);
      }
      unsigned int bal = __ballot_sync(0xFFFFFFFFu, pass);
      wmask |= ((unsigned long long)bal) << base;
    }

    float cm = 0.0f;
    int gbest = 0;
    while (wmask) {
      const int k = __ffsll((long long)wmask) - 1;
      wmask &= wmask - 1ull;
      const int g = s_tg[k];
      const float4 q = sq4[g];
      const float  ar = sarea[g];
      float iw = fmaxf(0.0f, __fsub_rn(fminf(q.w, an.w), fmaxf(q.y, an.y)));
      float ih = fmaxf(0.0f, __fsub_rn(fminf(q.z, an.z), fmaxf(q.x, an.x)));
      float inter = __fmul_rn(iw, ih);
      if (inter > 0.0f) {
        float v = __fdiv_rn(inter, __fsub_rn(__fadd_rn(ar, areaa), inter));
        if (v > cm) { cm = v; gbest = g; }
        unsigned long long key = ((unsigned long long)__float_as_uint(v) << 32)
                               | (unsigned long long)(0xFFFFFFFFu - (unsigned int)a);
        atomicMax(&s_rk[g], key);
      }
    }

    g_colmax[b][a] = cm;
    if (cm >= 0.7f) {
      g_argg[b][a] = gbest;
      unsigned int jj = (unsigned int)gbest * AA + (unsigned int)a;
      float u = jax_uniform(s_k1, jj);
      int idx = atomicAdd(&g_poscnt[b], 1);
      if (idx < POSCAP) { g_posj[b][idx] = (int)jj; g_posu[b][idx] = u; }
      unsigned long long xb = (unsigned long long)__float_as_uint(an.y);
      unsigned long long na = (unsigned long long)(0xFFFFFFFFu - (unsigned int)a);
      atomicMax(&s_lk[gbest], ((xb ^ 0xFFFFFFFFull) << 32) | na);
      atomicMax(&s_rr[gbest], (xb << 32) | na);
    } else if (cm < 0.5f) {
      negc++;
      float u = jax_uniform(s_k2, (unsigned int)a);
      if (u >= HITHRESH) {
        int idx = atomicAdd(&g_hicnt[b], 1);
        if (idx < HICAP) { g_hiv[b][idx] = u; g_hii[b][idx] = (int)a; }
      }
    }
  }

  if (negc) atomicAdd(&s_negc, negc);
  __syncthreads();
  for (int g = t; g < GG; g += 256) {
    if (s_rk[g]) atomicMax(&g_rowvk[b][g], s_rk[g]);
    if (s_lk[g]) atomicMax(&g_lx[b][g], s_lk[g]);
    if (s_rr[g]) atomicMax(&g_rx[b][g], s_rr[g]);
  }
  if (t == 0 && s_negc) atomicAdd(&g_negavail[b], s_negc);
}

// ---------------- helpers for kC ----------------
__device__ __forceinline__ unsigned long long mk_key(float u, unsigned int idx) {
  return ((unsigned long long)__float_as_uint(u) << 32)
       | (unsigned long long)(0xFFFFFFFFu - idx);
}

// exact top-k (sorted) over shared packed keys via rank counting. out[r] = idx.
__device__ void rank_select(const unsigned long long* s_ck, int M, int k, int* out, int t) {
  for (int i = t; i < M; i += 256) {
    const unsigned long long ki = s_ck[i];
    int r = 0;
    for (int j = 0; j < M; j++) r += (s_ck[j] > ki);
    if (r < k) out[r] = (int)(0xFFFFFFFFu - (unsigned int)(ki & 0xFFFFFFFFull));
  }
  __syncthreads();
}

__device__ __forceinline__ unsigned long long blk_max(unsigned long long v,
                                                      unsigned long long* s_part, int t) {
  for (int o = 16; o; o >>= 1) {
    unsigned long long w = __shfl_xor_sync(0xFFFFFFFFu, v, o);
    if (w > v) v = w;
  }
  if ((t & 31) == 0) s_part[t >> 5] = v;
  __syncthreads();
  if (t < 32) {
    unsigned long long w = (t < 8) ? s_part[t] : 0ull;
    for (int o = 4; o; o >>= 1) {
      unsigned long long x = __shfl_xor_sync(0xFFFFFFFFu, w, o);
      if (x > w) w = x;
    }
    if (t == 0) s_part[0] = w;
  }
  __syncthreads();
  unsigned long long r = s_part[0];
  __syncthreads();
  return r;
}

// slow global top-k (fallback only); val<0 skipped; idxarr==null -> identity
__device__ void topk_gl(const float* val, const int* idxarr, int cnt, int k, int* out,
                        unsigned long long* s_part, int t) {
  unsigned long long prev = 0xFFFFFFFFFFFFFFFFull;
  for (int s = 0; s < k; s++) {
    unsigned long long best = 0ull;
    for (int i = t; i < cnt; i += 256) {
      float v = val[i];
      if (v < 0.0f) continue;
      unsigned int id = idxarr ? (unsigned int)idxarr[i] : (unsigned int)i;
      unsigned long long key = mk_key(v, id);
      if (key < prev && key > best) best = key;
    }
    best = blk_max(best, s_part, t);
    prev = best;
    if (t == 0) out[s] = (int)(0xFFFFFFFFu - (unsigned int)(best & 0xFFFFFFFFull));
  }
  __syncthreads();
}

// ---------------- pass C: fused row pass + selection + assembly + reset ----
__global__ void kC(const float* __restrict__ gt_boxes, const float* __restrict__ gt_cls,
                   const float* __restrict__ anchors, const int* __restrict__ vai,
                   float* __restrict__ out) {
  const int b = blockIdx.x;
  const int t = threadIdx.x;
  __shared__ unsigned long long s_ck[MCAP];
  __shared__ unsigned long long s_part[8];
  __shared__ int   s_hist[NBK];
  __shared__ int   s_ctl[8];   // 0:compact 1:tb 2:ovf 3:stalecnt 4:poscnt 5:uniqstale
  __shared__ int   s_stale[64];
  __shared__ int   s_selj[PP];
  __shared__ float s_pd0[PP], s_pd1[PP], s_pc[PP];
  __shared__ int   s_ai[PP];
  __shared__ int   s_negi[NNEGK];
  __shared__ uint2 s_k1, s_k2;

  if (t < 8) s_ctl[t] = 0;
  if (t == 0) derive_keys(b, s_k1, s_k2);
  __syncthreads();

  // ---- fused row-winner pass (g = t) ----
  if (t < GG) {
    const int g = t;
    if (gt_boxes[((long)b * GG + g) * 5 + 4] > 0.0f) {
      unsigned long long rk = g_rowvk[b][g];
      if (rk) {
        unsigned int a = 0xFFFFFFFFu - (unsigned int)(rk & 0xFFFFFFFFull);
        float cma = g_colmax[b][a];
        bool dup = (cma >= 0.7f) && (g_argg[b][a] == g);
        if (!dup) {
          unsigned int jj = (unsigned int)g * AA + a;
          float u = jax_uniform(s_k1, jj);
          int idx = atomicAdd(&g_poscnt[b], 1);
          if (idx < POSCAP) { g_posj[b][idx] = (int)jj; g_posu[b][idx] = u; }
          unsigned long long xb =
            (unsigned long long)__float_as_uint(anchors[((long)b * AA + a) * 4 + 1]);
          unsigned long long na = (unsigned long long)(0xFFFFFFFFu - a);
          atomicMax(&g_lx[b][g], ((xb ^ 0xFFFFFFFFull) << 32) | na);
          atomicMax(&g_rx[b][g], (xb << 32) | na);
        }
        if (cma < 0.5f) {
          int k = atomicAdd(&s_ctl[3], 1);
          if (k < 64) s_stale[k] = (int)a;
        }
      }
    }
  }
  __syncthreads();
  if (t == 0) s_ctl[4] = atomicAdd(&g_poscnt[b], 0);
  __syncthreads();

  // ---- positives ----
  int cnt = s_ctl[4]; if (cnt > POSCAP) cnt = POSCAP;
  const int pos_num = cnt < PP ? cnt : PP;
  bool fb = false;
  int M = 0;
  if (cnt <= DIRECT) {
    for (int i = t; i < cnt; i += 256) s_ck[i] = mk_key(g_posu[b][i], (unsigned int)g_posj[b][i]);
    M = cnt;
    __syncthreads();
  } else {
    for (int i = t; i < NBK; i += 256) s_hist[i] = 0;
    __syncthreads();
    for (int i = t; i < cnt; i += 256) {
      int bk = (int)(g_posu[b][i] * (float)NBK);
      if (bk > NBK - 1) bk = NBK - 1;
      atomicAdd(&s_hist[bk], 1);
    }
    __syncthreads();
    if (t == 0) {
      int acc = 0, tb = 0;
      for (int i = NBK - 1; i >= 0; i--) { acc += s_hist[i]; if (acc >= PP) { tb = i; break; } }
      s_ctl[1] = tb;
      s_ctl[2] = (acc > MCAP) ? 1 : 0;
      s_ctl[0] = 0;
    }
    __syncthreads();
    if (s_ctl[2]) {
      fb = true;
    } else {
      int tb = s_ctl[1];
      for (int i = t; i < cnt; i += 256) {
        float u = g_posu[b][i];
        int bk = (int)(u * (float)NBK); if (bk > NBK - 1) bk = NBK - 1;
        if (bk >= tb) {
          int p = atomicAdd(&s_ctl[0], 1);
          s_ck[p] = mk_key(u, (unsigned int)g_posj[b][i]);
        }
      }
      __syncthreads();
      M = s_ctl[0];
    }
  }
  if (!fb) rank_select(s_ck, M, pos_num, s_selj, t);
  else     topk_gl(g_posu[b], g_posj[b], cnt, pos_num, s_selj, s_part, t);

  for (int s = t; s < pos_num; s += 256) {
    int j = s_selj[s];
    int g = j / AA;
    int a = j - g * AA;
    const float* pa = anchors + ((long)b * AA + a) * 4;
    const float* pg = gt_boxes + ((long)b * GG + g) * 5;
    float h   = pa[2] - pa[0];
    float gth = pg[2] - pg[0];
    float dy  = (pg[2] + pg[0] - (pa[2] + pa[0])) * 0.5f / h;
    float dh  = logf(gth / h);
    s_pd0[s] = dy / 0.1f;
    s_pd1[s] = dh / 0.2f;
    s_pc[s]  = gt_cls[((long)b * GG + g) * 2];
    s_ai[s]  = a;
  }
  __syncthreads();

  // ---- negatives ----
  int sc = s_ctl[3]; if (sc > 64) sc = 64;
  if (t == 0) { s_ctl[0] = 0; s_ctl[2] = 0; }
  __syncthreads();
  int hic = g_hicnt[b]; if (hic > HICAP) hic = HICAP;
  for (int i = t; i < hic; i += 256) {
    int a = g_hii[b][i];
    bool ok = true;
    for (int k = 0; k < sc; k++) if (s_stale[k] == a) { ok = false; break; }
    if (ok) {
      int p = atomicAdd(&s_ctl[0], 1);
      if (p < MCAP) s_ck[p] = mk_key(g_hiv[b][i], (unsigned int)a);
      else s_ctl[2] = 1;
    }
  }
  __syncthreads();
  int hice = s_ctl[0]; if (hice > MCAP) hice = MCAP;
  int neg_num;
  if (hice >= NNEGK && !s_ctl[2]) {
    neg_num = NNEGK;
    rank_select(s_ck, hice, NNEGK, s_negi, t);
  } else {
    if (t == 0) {   // unique stale count
      int u = 0;
      for (int i = 0; i < sc; i++) {
        bool first = true;
        for (int j = 0; j < i; j++) if (s_stale[j] == s_stale[i]) { first = false; break; }
        u += first;
      }
      s_ctl[5] = u;
    }
    __syncthreads();
    int avail = g_negavail[b] - s_ctl[5];
    neg_num = avail < NNEGK ? avail : NNEGK;
    if (neg_num > TT - pos_num) neg_num = TT - pos_num;
    if (neg_num < 0) neg_num = 0;
    for (int a = t; a < AA; a += 256) {
      float ns = -1.0f;
      if (g_colmax[b][a] < 0.5f) {
        bool ok = true;
        for (int k = 0; k < sc; k++) if (s_stale[k] == a) { ok = false; break; }
        if (ok) ns = jax_uniform(s_k2, (unsigned int)a);
      }
      g_fbu[b][a] = ns;
    }
    __syncthreads();
    topk_gl(g_fbu[b], nullptr, AA, neg_num, s_negi, s_part, t);
  }

  // ---- assembly ----
  const int OFF_DELTAS = 0;
  const int OFF_CLS = BB * TT * 3;
  const int OFF_IND = OFF_CLS + BB * TT * 2;
  const int OFF_SD  = OFF_IND + BB * TT * 2;
  const int OFF_SI  = OFF_SD + BB * GG * 3;
  const int OFF_GTN = OFF_SI + BB * GG * 3;
  const int OFF_PN  = OFF_GTN + BB;
  const int OFF_NN  = OFF_PN + BB;

  for (int i = t; i < TT; i += 256) {
    bool isp = i < pos_num;
    bool isn = !isp && (i < pos_num + neg_num);
    float tagc = (isp || isn) ? 1.0f : 0.0f;
    float* dd = out + OFF_DELTAS + ((long)b * TT + i) * 3;
    dd[0] = isp ? s_pd0[i] : 0.0f;
    dd[1] = isp ? s_pd1[i] : 0.0f;
    dd[2] = tagc;
    float* dc = out + OFF_CLS + ((long)b * TT + i) * 2;
    dc[0] = isp ? s_pc[i] : 0.0f;
    dc[1] = tagc;
    int ind = 0;
    if (isp)      ind = vai[(long)b * AA + s_ai[i]];
    else if (isn) ind = s_negi[i - pos_num];
    float* di = out + OFF_IND + ((long)b * TT + i) * 2;
    di[0] = (float)ind;
    di[1] = isp ? 1.0f : (isn ? -1.0f : 0.0f);
  }

  for (int g = t; g < GG; g += 256) {
    const float* pg = gt_boxes + ((long)b * GG + g) * 5;
    float* sd = out + OFF_SD + ((long)b * GG + g) * 3;
    float* si = out + OFF_SI + ((long)b * GG + g) * 3;
    if (pg[4] > 0.0f) {
      unsigned long long lk = g_lx[b][g];
      unsigned long long rk = g_rx[b][g];
      unsigned int la_u = 0xFFFFFFFFu ^ (unsigned int)(lk & 0xFFFFFFFFull);
      unsigned int ra_u = 0xFFFFFFFFu - (unsigned int)(rk & 0xFFFFFFFFull);
      int la_i = (la_u < AA) ? (int)la_u : 0;
      int ra_i = (ra_u < AA) ? (int)ra_u : 0;
      const float* la = anchors + ((long)b * AA + la_i) * 4;
      const float* ra = anchors + ((long)b * AA + ra_i) * 4;
      float ld = (pg[1] - (la[3] + la[1]) * 0.5f) / (la[3] - la[1]) / 0.1f;
      float rd = (pg[3] - (ra[3] + ra[1]) * 0.5f) / (ra[3] - ra[1]) / 0.1f;
      sd[0] = ld; sd[1] = rd; sd[2] = 1.0f;
      si[0] = (float)vai[(long)b * AA + la_i];
      si[1] = (float)vai[(long)b * AA + ra_i];
      si[2] = 1.0f;
    } else {
      sd[0] = 0.0f; sd[1] = 0.0f; sd[2] = 0.0f;
      si[0] = 0.0f; si[1] = 0.0f; si[2] = 0.0f;
    }
  }

  if (t == 0) {
    float gtn = 0.0f;
    for (int g = 0; g < GG; g++)
      if (gt_boxes[((long)b * GG + g) * 5 + 4] > 0.0f) gtn += 1.0f;
    out[OFF_GTN + b] = gtn;
    out[OFF_PN + b]  = (float)pos_num;
    out[OFF_NN + b]  = (float)neg_num;
  }

  // ---- reset this image's reducers for the next replay ----
  __syncthreads();
  for (int g = t; g < GG; g += 256) {
    g_rowvk[b][g] = 0ull;
    g_lx[b][g]    = 0ull;
    g_rx[b][g]    = 0ull;
  }
  if (t == 0) { g_poscnt[b] = 0; g_hicnt[b] = 0; g_negavail[b] = 0; }
}

extern "C" void kernel_launch(void* const* d_in, const int* in_sizes, int n_in,
                              void* d_out, int out_size) {
  const float* gt_boxes = (const float*)d_in[0];   // (B, 50, 5)
  const float* gt_cls   = (const float*)d_in[1];   // (B, 50, 2)
  const float* anchors  = (const float*)d_in[2];   // (B, 81920, 4)
  const int*   vai      = (const int*)d_in[3];     // (B, 81920)
  float* out = (float*)d_out;

  dim3 gridA(AA / APB, BB);
  kA<<<gridA, 256>>>(gt_boxes, anchors);
  kC<<<BB, 256>>>(gt_boxes, gt_cls, anchors, vai, out);
}

// round 15
// speedup vs baseline: 1.0734x; 1.0734x over previous
#include <cuda_runtime.h>

#define BB 16
#define GG 50
#define AA 81920
#define TT 128
#define PP 64
#define NNEGK 64
#define POSCAP 65536
#define HICAP 4096
#define HITHRESH 0.998f
#define NBK 512
#define MCAP 1024
#define DIRECT 1024
#define APB 2048           // anchors per kA block
#define RPT (APB / 256)    // rounds per thread (8)
#define CT 1024            // kC threads

// ---------------- device scratch (static, zero-init at load; kC resets) ----
static __device__ float              g_colmax[BB][AA];
static __device__ int                g_argg[BB][AA];      // valid only when cm>=0.7
static __device__ unsigned long long g_rowvk[BB][GG];     // (v_bits<<32)|(~a)      max
static __device__ unsigned long long g_lx[BB][GG];        // (~x1_bits<<32)|(~a)    max (== min x1, min a)
static __device__ unsigned long long g_rx[BB][GG];        // (x1_bits<<32)|(~a)     max
static __device__ int                g_poscnt[BB];
static __device__ int                g_posj[BB][POSCAP];
static __device__ float              g_posu[BB][POSCAP];
static __device__ int                g_hicnt[BB];
static __device__ float              g_hiv[BB][HICAP];
static __device__ int                g_hii[BB][HICAP];
static __device__ int                g_negavail[BB];
static __device__ float              g_fbu[BB][AA];       // fallback-only scratch

// ---------------- threefry2x32 (JAX partitionable) ----------------
__device__ __forceinline__ void threefry2x32(unsigned int k0, unsigned int k1,
                                             unsigned int x0, unsigned int x1,
                                             unsigned int &o0, unsigned int &o1) {
  const unsigned int ks0 = k0, ks1 = k1, ks2 = k0 ^ k1 ^ 0x1BD11BDAu;
  unsigned int v0 = x0 + ks0, v1 = x1 + ks1;
#define TFR(r) { v0 += v1; v1 = (v1 << (r)) | (v1 >> (32 - (r))); v1 ^= v0; }
  TFR(13) TFR(15) TFR(26) TFR(6)   v0 += ks1; v1 += ks2 + 1u;
  TFR(17) TFR(29) TFR(16) TFR(24)  v0 += ks2; v1 += ks0 + 2u;
  TFR(13) TFR(15) TFR(26) TFR(6)   v0 += ks0; v1 += ks1 + 3u;
  TFR(17) TFR(29) TFR(16) TFR(24)  v0 += ks1; v1 += ks2 + 4u;
  TFR(13) TFR(15) TFR(26) TFR(6)   v0 += ks2; v1 += ks0 + 5u;
#undef TFR
  o0 = v0; o1 = v1;
}

__device__ __forceinline__ float jax_uniform(uint2 key, unsigned int idx) {
  unsigned int o0, o1;
  threefry2x32(key.x, key.y, 0u, idx, o0, o1);
  unsigned int bits = o0 ^ o1;
  return __uint_as_float((bits >> 9) | 0x3F800000u) - 1.0f;
}

// keys = split(key(42), B); k1,k2 = split(keys[b])
__device__ __forceinline__ void derive_keys(int b, uint2 &k1, uint2 &k2) {
  unsigned int kb0, kb1, a0, a1, c0, c1;
  threefry2x32(0u, 42u, 0u, (unsigned int)b, kb0, kb1);
  threefry2x32(kb0, kb1, 0u, 0u, a0, a1);
  threefry2x32(kb0, kb1, 0u, 1u, c0, c1);
  k1 = make_uint2(a0, a1);
  k2 = make_uint2(c0, c1);
}

// ---------------- 8-bit Morton cell of (y1, x1): 16x16 grid ----------------
__device__ __forceinline__ int cell8(float y1, float x1) {
  int by = (int)(y1 * (16.0f / 961.0f));
  int bx = (int)(x1 * (16.0f / 1001.0f));
  by = by < 0 ? 0 : (by > 15 ? 15 : by);
  bx = bx < 0 ? 0 : (bx > 15 ? 15 : bx);
  int m = 0;
  #pragma unroll
  for (int i = 0; i < 4; i++)
    m |= (((by >> i) & 1) << (2 * i + 1)) | (((bx >> i) & 1) << (2 * i));
  return m;
}

// ---- pass A: in-block Morton sort (2048 anchors) + warp-coherent IoU ------
__global__ void kA(const float* __restrict__ gt_boxes, const float* __restrict__ anchors) {
  const int b = blockIdx.y;
  const int t = threadIdx.x;
  const int abase = blockIdx.x * APB;
  __shared__ float4 sq4[GG];     // (y1, x1, y2, x2)
  __shared__ float  sarea[GG];
  __shared__ int    s_tg[GG];
  __shared__ int    s_nt;
  __shared__ int    s_negc;
  __shared__ unsigned long long s_rk[GG];
  __shared__ unsigned long long s_lk[GG];   // complemented encoding, max
  __shared__ unsigned long long s_rr[GG];
  __shared__ uint2  s_k1, s_k2;
  __shared__ unsigned short scell[APB];
  __shared__ unsigned short sperm[APB];
  __shared__ int    shist[256];

  if (t == 0) { s_nt = 0; s_negc = 0; derive_keys(b, s_k1, s_k2); }
  shist[t] = 0;
  __syncthreads();
  for (int g = t; g < GG; g += 256) {
    const float* gp = gt_boxes + ((long)b * GG + g) * 5;
    float q0 = gp[0], q1 = gp[1], q2 = gp[2], q3 = gp[3], tg = gp[4];
    sq4[g] = make_float4(q0, q1, q2, q3);
    sarea[g] = __fmul_rn(__fsub_rn(q3, q1), __fsub_rn(q2, q0));
    s_rk[g] = 0ull; s_lk[g] = 0ull; s_rr[g] = 0ull;
    if (tg > 0.0f) { int k = atomicAdd(&s_nt, 1); s_tg[k] = g; }
  }
  __syncthreads();

  const float4* ap = reinterpret_cast<const float4*>(anchors) + (long)b * AA;

  // ---- pass 1: local histogram (coalesced anchor loads) ----
  #pragma unroll
  for (int r = 0; r < RPT; r++) {
    const int i = r * 256 + t;
    const float4 an = ap[abase + i];
    const int c = cell8(an.x, an.y);
    scell[i] = (unsigned short)c;
    atomicAdd(&shist[c], 1);
  }
  __syncthreads();

  // ---- exclusive scan over 256 bins (Hillis-Steele) ----
  const int cnt0 = shist[t];
  int val = cnt0;
  for (int off = 1; off < 256; off <<= 1) {
    int y = (t >= off) ? shist[t - off] : 0;
    __syncthreads();
    val += y;
    shist[t] = val;
    __syncthreads();
  }
  const int ebase = val - cnt0;
  __syncthreads();
  shist[t] = ebase;
  __syncthreads();

  // ---- pass 2: scatter local permutation ----
  #pragma unroll
  for (int r = 0; r < RPT; r++) {
    const int i = r * 256 + t;
    const int slot = atomicAdd(&shist[scell[i]], 1);
    sperm[slot] = (unsigned short)i;
  }
  __syncthreads();

  // ---- main: 8 rounds of warp-coherent processing ----
  const int nt = s_nt;
  const int lane = t & 31;
  int negc = 0;
  #pragma unroll 1
  for (int r = 0; r < RPT; r++) {
    const int a = abase + (int)sperm[r * 256 + t];
    const float4 an = ap[a];                 // gather; L1-resident
    const float areaa = __fmul_rn(__fsub_rn(an.w, an.y), __fsub_rn(an.z, an.x));

    // warp bounding box (coords >= 0: float bits order-preserving)
    const float wy1min = __uint_as_float(__reduce_min_sync(0xFFFFFFFFu, __float_as_uint(an.x)));
    const float wy2max = __uint_as_float(__reduce_max_sync(0xFFFFFFFFu, __float_as_uint(an.z)));
    const float wx1min = __uint_as_float(__reduce_min_sync(0xFFFFFFFFu, __float_as_uint(an.y)));
    const float wx2max = __uint_as_float(__reduce_max_sync(0xFFFFFFFFu, __float_as_uint(an.w)));

    // per-warp GT survival mask via ballots
    unsigned long long wmask = 0ull;
    for (int base = 0; base < nt; base += 32) {
      int k = base + lane;
      bool pass = false;
      if (k < nt) {
        const float4 q = sq4[s_tg[k]];
        pass = (q.w > wx1min) && (wx2max > q.y) && (q.z > wy1min) && (wy2max > q.x);
      }
      unsigned int bal = __ballot_sync(0xFFFFFFFFu, pass);
      wmask |= ((unsigned long long)bal) << base;
    }

    float cm = 0.0f;
    int gbest = 0;
    while (wmask) {
      const int k = __ffsll((long long)wmask) - 1;
      wmask &= wmask - 1ull;
      const int g = s_tg[k];
      const float4 q = sq4[g];
      const float  ar = sarea[g];
      float iw = fmaxf(0.0f, __fsub_rn(fminf(q.w, an.w), fmaxf(q.y, an.y)));
      float ih = fmaxf(0.0f, __fsub_rn(fminf(q.z, an.z), fmaxf(q.x, an.x)));
      float inter = __fmul_rn(iw, ih);
      if (inter > 0.0f) {
        float v = __fdiv_rn(inter, __fsub_rn(__fadd_rn(ar, areaa), inter));
        if (v > cm) { cm = v; gbest = g; }
        unsigned long long key = ((unsigned long long)__float_as_uint(v) << 32)
                               | (unsigned long long)(0xFFFFFFFFu - (unsigned int)a);
        atomicMax(&s_rk[g], key);
      }
    }

    g_colmax[b][a] = cm;
    if (cm >= 0.7f) {
      g_argg[b][a] = gbest;
      unsigned int jj = (unsigned int)gbest * AA + (unsigned int)a;
      float u = jax_uniform(s_k1, jj);
      int idx = atomicAdd(&g_poscnt[b], 1);
      if (idx < POSCAP) { g_posj[b][idx] = (int)jj; g_posu[b][idx] = u; }
      unsigned long long xb = (unsigned long long)__float_as_uint(an.y);
      unsigned long long na = (unsigned long long)(0xFFFFFFFFu - (unsigned int)a);
      atomicMax(&s_lk[gbest], ((xb ^ 0xFFFFFFFFull) << 32) | na);
      atomicMax(&s_rr[gbest], (xb << 32) | na);
    } else if (cm < 0.5f) {
      negc++;
      float u = jax_uniform(s_k2, (unsigned int)a);
      if (u >= HITHRESH) {
        int idx = atomicAdd(&g_hicnt[b], 1);
        if (idx < HICAP) { g_hiv[b][idx] = u; g_hii[b][idx] = (int)a; }
      }
    }
  }

  if (negc) atomicAdd(&s_negc, negc);
  __syncthreads();
  for (int g = t; g < GG; g += 256) {
    if (s_rk[g]) atomicMax(&g_rowvk[b][g], s_rk[g]);
    if (s_lk[g]) atomicMax(&g_lx[b][g], s_lk[g]);
    if (s_rr[g]) atomicMax(&g_rx[b][g], s_rr[g]);
  }
  if (t == 0 && s_negc) atomicAdd(&g_negavail[b], s_negc);
}

// ---------------- helpers for kC (CT = 1024 threads) ----------------
__device__ __forceinline__ unsigned long long mk_key(float u, unsigned int idx) {
  return ((unsigned long long)__float_as_uint(u) << 32)
       | (unsigned long long)(0xFFFFFFFFu - idx);
}

// exact top-k (sorted) over shared packed keys via rank counting. out[r] = idx.
__device__ void rank_select(const unsigned long long* s_ck, int M, int k, int* out, int t) {
  for (int i = t; i < M; i += CT) {
    const unsigned long long ki = s_ck[i];
    int r = 0;
    for (int j = 0; j < M; j++) r += (s_ck[j] > ki);
    if (r < k) out[r] = (int)(0xFFFFFFFFu - (unsigned int)(ki & 0xFFFFFFFFull));
  }
  __syncthreads();
}

__device__ __forceinline__ unsigned long long blk_max(unsigned long long v,
                                                      unsigned long long* s_part, int t) {
  for (int o = 16; o; o >>= 1) {
    unsigned long long w = __shfl_xor_sync(0xFFFFFFFFu, v, o);
    if (w > v) v = w;
  }
  if ((t & 31) == 0) s_part[t >> 5] = v;
  __syncthreads();
  if (t < 32) {
    unsigned long long w = s_part[t];           // 32 warps -> 32 partials
    for (int o = 16; o; o >>= 1) {
      unsigned long long x = __shfl_xor_sync(0xFFFFFFFFu, w, o);
      if (x > w) w = x;
    }
    if (t == 0) s_part[0] = w;
  }
  __syncthreads();
  unsigned long long r = s_part[0];
  __syncthreads();
  return r;
}

// slow global top-k (fallback only); val<0 skipped; idxarr==null -> identity
__device__ void topk_gl(const float* val, const int* idxarr, int cnt, int k, int* out,
                        unsigned long long* s_part, int t) {
  unsigned long long prev = 0xFFFFFFFFFFFFFFFFull;
  for (int s = 0; s < k; s++) {
    unsigned long long best = 0ull;
    for (int i = t; i < cnt; i += CT) {
      float v = val[i];
      if (v < 0.0f) continue;
      unsigned int id = idxarr ? (unsigned int)idxarr[i] : (unsigned int)i;
      unsigned long long key = mk_key(v, id);
      if (key < prev && key > best) best = key;
    }
    best = blk_max(best, s_part, t);
    prev = best;
    if (t == 0) out[s] = (int)(0xFFFFFFFFu - (unsigned int)(best & 0xFFFFFFFFull));
  }
  __syncthreads();
}

// ---------------- pass C: fused row pass + selection + assembly + reset ----
__global__ __launch_bounds__(CT)
void kC(const float* __restrict__ gt_boxes, const float* __restrict__ gt_cls,
        const float* __restrict__ anchors, const int* __restrict__ vai,
        float* __restrict__ out) {
  const int b = blockIdx.x;
  const int t = threadIdx.x;
  __shared__ unsigned long long s_ck[MCAP];
  __shared__ unsigned long long s_part[32];
  __shared__ int   s_hist[NBK];
  __shared__ int   s_ctl[8];   // 0:compact 1:tb 2:ovf 3:stalecnt 4:poscnt 5:uniqstale
  __shared__ int   s_stale[64];
  __shared__ int   s_selj[PP];
  __shared__ float s_pd0[PP], s_pd1[PP], s_pc[PP];
  __shared__ int   s_ai[PP];
  __shared__ int   s_negi[NNEGK];
  __shared__ uint2 s_k1, s_k2;

  if (t < 8) s_ctl[t] = 0;
  if (t == 0) derive_keys(b, s_k1, s_k2);
  __syncthreads();

  // ---- fused row-winner pass (g = t) ----
  if (t < GG) {
    const int g = t;
    if (gt_boxes[((long)b * GG + g) * 5 + 4] > 0.0f) {
      unsigned long long rk = g_rowvk[b][g];
      if (rk) {
        unsigned int a = 0xFFFFFFFFu - (unsigned int)(rk & 0xFFFFFFFFull);
        float cma = g_colmax[b][a];
        bool dup = (cma >= 0.7f) && (g_argg[b][a] == g);
        if (!dup) {
          unsigned int jj = (unsigned int)g * AA + a;
          float u = jax_uniform(s_k1, jj);
          int idx = atomicAdd(&g_poscnt[b], 1);
          if (idx < POSCAP) { g_posj[b][idx] = (int)jj; g_posu[b][idx] = u; }
          unsigned long long xb =
            (unsigned long long)__float_as_uint(anchors[((long)b * AA + a) * 4 + 1]);
          unsigned long long na = (unsigned long long)(0xFFFFFFFFu - a);
          atomicMax(&g_lx[b][g], ((xb ^ 0xFFFFFFFFull) << 32) | na);
          atomicMax(&g_rx[b][g], (xb << 32) | na);
        }
        if (cma < 0.5f) {
          int k = atomicAdd(&s_ctl[3], 1);
          if (k < 64) s_stale[k] = (int)a;
        }
      }
    }
  }
  __syncthreads();
  if (t == 0) s_ctl[4] = atomicAdd(&g_poscnt[b], 0);
  __syncthreads();

  // ---- positives ----
  int cnt = s_ctl[4]; if (cnt > POSCAP) cnt = POSCAP;
  const int pos_num = cnt < PP ? cnt : PP;
  bool fb = false;
  int M = 0;
  if (cnt <= DIRECT) {
    for (int i = t; i < cnt; i += CT) s_ck[i] = mk_key(g_posu[b][i], (unsigned int)g_posj[b][i]);
    M = cnt;
    __syncthreads();
  } else {
    for (int i = t; i < NBK; i += CT) s_hist[i] = 0;
    __syncthreads();
    for (int i = t; i < cnt; i += CT) {
      int bk = (int)(g_posu[b][i] * (float)NBK);
      if (bk > NBK - 1) bk = NBK - 1;
      atomicAdd(&s_hist[bk], 1);
    }
    __syncthreads();
    if (t == 0) {
      int acc = 0, tb = 0;
      for (int i = NBK - 1; i >= 0; i--) { acc += s_hist[i]; if (acc >= PP) { tb = i; break; } }
      s_ctl[1] = tb;
      s_ctl[2] = (acc > MCAP) ? 1 : 0;
      s_ctl[0] = 0;
    }
    __syncthreads();
    if (s_ctl[2]) {
      fb = true;
    } else {
      int tb = s_ctl[1];
      for (int i = t; i < cnt; i += CT) {
        float u = g_posu[b][i];
        int bk = (int)(u * (float)NBK); if (bk > NBK - 1) bk = NBK - 1;
        if (bk >= tb) {
          int p = atomicAdd(&s_ctl[0], 1);
          s_ck[p] = mk_key(u, (unsigned int)g_posj[b][i]);
        }
      }
      __syncthreads();
      M = s_ctl[0];
    }
  }
  if (!fb) rank_select(s_ck, M, pos_num, s_selj, t);
  else     topk_gl(g_posu[b], g_posj[b], cnt, pos_num, s_selj, s_part, t);

  for (int s = t; s < pos_num; s += CT) {
    int j = s_selj[s];
    int g = j / AA;
    int a = j - g * AA;
    const float* pa = anchors + ((long)b * AA + a) * 4;
    const float* pg = gt_boxes + ((long)b * GG + g) * 5;
    float h   = pa[2] - pa[0];
    float gth = pg[2] - pg[0];
    float dy  = (pg[2] + pg[0] - (pa[2] + pa[0])) * 0.5f / h;
    float dh  = logf(gth / h);
    s_pd0[s] = dy / 0.1f;
    s_pd1[s] = dh / 0.2f;
    s_pc[s]  = gt_cls[((long)b * GG + g) * 2];
    s_ai[s]  = a;
  }
  __syncthreads();

  // ---- negatives ----
  int sc = s_ctl[3]; if (sc > 64) sc = 64;
  if (t == 0) { s_ctl[0] = 0; s_ctl[2] = 0; }
  __syncthreads();
  int hic = g_hicnt[b]; if (hic > HICAP) hic = HICAP;
  for (int i = t; i < hic; i += CT) {
    int a = g_hii[b][i];
    bool ok = true;
    for (int k = 0; k < sc; k++) if (s_stale[k] == a) { ok = false; break; }
    if (ok) {
      int p = atomicAdd(&s_ctl[0], 1);
      if (p < MCAP) s_ck[p] = mk_key(g_hiv[b][i], (unsigned int)a);
      else s_ctl[2] = 1;
    }
  }
  __syncthreads();
  int hice = s_ctl[0]; if (hice > MCAP) hice = MCAP;
  int neg_num;
  if (hice >= NNEGK && !s_ctl[2]) {
    neg_num = NNEGK;
    rank_select(s_ck, hice, NNEGK, s_negi, t);
  } else {
    if (t == 0) {   // unique stale count
      int u = 0;
      for (int i = 0; i < sc; i++) {
        bool first = true;
        for (int j = 0; j < i; j++) if (s_stale[j] == s_stale[i]) { first = false; break; }
        u += first;
      }
      s_ctl[5] = u;
    }
    __syncthreads();
    int avail = g_negavail[b] - s_ctl[5];
    neg_num = avail < NNEGK ? avail : NNEGK;
    if (neg_num > TT - pos_num) neg_num = TT - pos_num;
    if (neg_num < 0) neg_num = 0;
    for (int a = t; a < AA; a += CT) {
      float ns = -1.0f;
      if (g_colmax[b][a] < 0.5f) {
        bool ok = true;
        for (int k = 0; k < sc; k++) if (s_stale[k] == a) { ok = false; break; }
        if (ok) ns = jax_uniform(s_k2, (unsigned int)a);
      }
      g_fbu[b][a] = ns;
    }
    __syncthreads();
    topk_gl(g_fbu[b], nullptr, AA, neg_num, s_negi, s_part, t);
  }

  // ---- assembly ----
  const int OFF_DELTAS = 0;
  const int OFF_CLS = BB * TT * 3;
  const int OFF_IND = OFF_CLS + BB * TT * 2;
  const int OFF_SD  = OFF_IND + BB * TT * 2;
  const int OFF_SI  = OFF_SD + BB * GG * 3;
  const int OFF_GTN = OFF_SI + BB * GG * 3;
  const int OFF_PN  = OFF_GTN + BB;
  const int OFF_NN  = OFF_PN + BB;

  for (int i = t; i < TT; i += CT) {
    bool isp = i < pos_num;
    bool isn = !isp && (i < pos_num + neg_num);
    float tagc = (isp || isn) ? 1.0f : 0.0f;
    float* dd = out + OFF_DELTAS + ((long)b * TT + i) * 3;
    dd[0] = isp ? s_pd0[i] : 0.0f;
    dd[1] = isp ? s_pd1[i] : 0.0f;
    dd[2] = tagc;
    float* dc = out + OFF_CLS + ((long)b * TT + i) * 2;
    dc[0] = isp ? s_pc[i] : 0.0f;
    dc[1] = tagc;
    int ind = 0;
    if (isp)      ind = vai[(long)b * AA + s_ai[i]];
    else if (isn) ind = s_negi[i - pos_num];
    float* di = out + OFF_IND + ((long)b * TT + i) * 2;
    di[0] = (float)ind;
    di[1] = isp ? 1.0f : (isn ? -1.0f : 0.0f);
  }

  for (int g = t; g < GG; g += CT) {
    const float* pg = gt_boxes + ((long)b * GG + g) * 5;
    float* sd = out + OFF_SD + ((long)b * GG + g) * 3;
    float* si = out + OFF_SI + ((long)b * GG + g) * 3;
    if (pg[4] > 0.0f) {
      unsigned long long lk = g_lx[b][g];
      unsigned long long rk = g_rx[b][g];
      unsigned int la_u = 0xFFFFFFFFu ^ (unsigned int)(lk & 0xFFFFFFFFull);
      unsigned int ra_u = 0xFFFFFFFFu - (unsigned int)(rk & 0xFFFFFFFFull);
      int la_i = (la_u < AA) ? (int)la_u : 0;
      int ra_i = (ra_u < AA) ? (int)ra_u : 0;
      const float* la = anchors + ((long)b * AA + la_i) * 4;
      const float* ra = anchors + ((long)b * AA + ra_i) * 4;
      float ld = (pg[1] - (la[3] + la[1]) * 0.5f) / (la[3] - la[1]) / 0.1f;
      float rd = (pg[3] - (ra[3] + ra[1]) * 0.5f) / (ra[3] - ra[1]) / 0.1f;
      sd[0] = ld; sd[1] = rd; sd[2] = 1.0f;
      si[0] = (float)vai[(long)b * AA + la_i];
      si[1] = (float)vai[(long)b * AA + ra_i];
      si[2] = 1.0f;
    } else {
      sd[0] = 0.0f; sd[1] = 0.0f; sd[2] = 0.0f;
      si[0] = 0.0f; si[1] = 0.0f; si[2] = 0.0f;
    }
  }

  if (t == 0) {
    float gtn = 0.0f;
    for (int g = 0; g < GG; g++)
      if (gt_boxes[((long)b * GG + g) * 5 + 4] > 0.0f) gtn += 1.0f;
    out[OFF_GTN + b] = gtn;
    out[OFF_PN + b]  = (float)pos_num;
    out[OFF_NN + b]  = (float)neg_num;
  }

  // ---- reset this image's reducers for the next replay ----
  __syncthreads();
  for (int g = t; g < GG; g += CT) {
    g_rowvk[b][g] = 0ull;
    g_lx[b][g]    = 0ull;
    g_rx[b][g]    = 0ull;
  }
  if (t == 0) { g_poscnt[b] = 0; g_hicnt[b] = 0; g_negavail[b] = 0; }
}

extern "C" void kernel_launch(void* const* d_in, const int* in_sizes, int n_in,
                              void* d_out, int out_size) {
  const float* gt_boxes = (const float*)d_in[0];   // (B, 50, 5)
  const float* gt_cls   = (const float*)d_in[1];   // (B, 50, 2)
  const float* anchors  = (const float*)d_in[2];   // (B, 81920, 4)
  const int*   vai      = (const int*)d_in[3];     // (B, 81920)
  float* out = (float*)d_out;

  dim3 gridA(AA / APB, BB);
  kA<<<gridA, 256>>>(gt_boxes, anchors);
  kC<<<BB, CT>>>(gt_boxes, gt_cls, anchors, vai, out);
}